// round 2
// baseline (speedup 1.0000x reference)
#include <cuda_runtime.h>
#include <cuda_fp16.h>
#include <stdint.h>

// Problem constants (B=2,H=16,S=2048,DK=DV=64)
#define SQ    2048
#define DHD   64
#define NBH   32          // B*H
#define BLKM  64          // Q rows per CTA
#define BLKN  64          // K cols per iteration
#define NITER (SQ/BLKN)   // 32
#define KPAD  72          // halves per smem row (conflict-free ldmatrix)
#define WPR   (SQ/32)     // packed mask words per row = 64
#define NWORDS (NBH*SQ*WPR)   // 4,194,304 words = 16.8 MB

// device scratch (no allocation allowed in kernel_launch)
__device__ __half   g_q16[(size_t)NBH*SQ*DHD];
__device__ __half   g_k16[(size_t)NBH*SQ*DHD];
__device__ __half   g_v16[(size_t)NBH*SQ*DHD];
__device__ uint32_t g_pmask[NWORDS];
__device__ int      g_mask_i32;

// ---- detect mask dtype: int32-bool words are always 0/1; u8-bool words are >1 w.p. 7/8 ----
__global__ void detect_kernel(const uint32_t* __restrict__ m) {
    __shared__ int anyBig;
    if (threadIdx.x == 0) anyBig = 0;
    __syncthreads();
    if (m[threadIdx.x] > 1u) anyBig = 1;   // benign race: only ever sets 1
    __syncthreads();
    if (threadIdx.x == 0) g_mask_i32 = (anyBig == 0);
}

// ---- bit-pack mask (either dtype) into g_pmask: bit e of word w = element 32w+e ----
__global__ void pack_kernel(const void* __restrict__ mraw) {
    int w = blockIdx.x * blockDim.x + threadIdx.x;
    if (w >= NWORDS) return;
    uint32_t bits = 0;
    if (g_mask_i32) {
        const uint4* p = (const uint4*)mraw + (size_t)w * 8;   // 32 ints
        #pragma unroll
        for (int i = 0; i < 8; i++) {
            uint4 v = p[i];
            bits |= ((v.x != 0u) ? 1u : 0u) << (4*i)
                 |  ((v.y != 0u) ? 1u : 0u) << (4*i + 1)
                 |  ((v.z != 0u) ? 1u : 0u) << (4*i + 2)
                 |  ((v.w != 0u) ? 1u : 0u) << (4*i + 3);
        }
    } else {
        const uint4* p = (const uint4*)mraw + (size_t)w * 2;   // 32 bytes
        #pragma unroll
        for (int i = 0; i < 2; i++) {
            uint4 v = p[i];
            uint32_t ws[4] = {v.x, v.y, v.z, v.w};
            #pragma unroll
            for (int b = 0; b < 4; b++) {
                uint32_t u = ws[b];
                int base = 16*i + 4*b;
                bits |= ((u & 0x000000FFu) ? 1u : 0u) << base
                     |  ((u & 0x0000FF00u) ? 1u : 0u) << (base + 1)
                     |  ((u & 0x00FF0000u) ? 1u : 0u) << (base + 2)
                     |  ((u & 0xFF000000u) ? 1u : 0u) << (base + 3);
            }
        }
    }
    g_pmask[w] = bits;
}

__global__ void cvt_all_kernel(const float* __restrict__ q,
                               const float* __restrict__ k,
                               const float* __restrict__ v) {
    const int n4 = NBH*SQ*DHD/4;
    int i = blockIdx.x*blockDim.x + threadIdx.x;
    if (i < n4) {
        float4 f;
        f = ((const float4*)q)[i];
        ((__half2*)g_q16)[2*i]   = __floats2half2_rn(f.x, f.y);
        ((__half2*)g_q16)[2*i+1] = __floats2half2_rn(f.z, f.w);
        f = ((const float4*)k)[i];
        ((__half2*)g_k16)[2*i]   = __floats2half2_rn(f.x, f.y);
        ((__half2*)g_k16)[2*i+1] = __floats2half2_rn(f.z, f.w);
        f = ((const float4*)v)[i];
        ((__half2*)g_v16)[2*i]   = __floats2half2_rn(f.x, f.y);
        ((__half2*)g_v16)[2*i+1] = __floats2half2_rn(f.z, f.w);
    }
}

__device__ __forceinline__ uint32_t smem_u32(const void* p) {
    return (uint32_t)__cvta_generic_to_shared(p);
}
__device__ __forceinline__ void ldmx4(uint32_t& r0, uint32_t& r1, uint32_t& r2, uint32_t& r3, uint32_t a) {
    asm volatile("ldmatrix.sync.aligned.m8n8.x4.shared.b16 {%0,%1,%2,%3}, [%4];\n"
                 : "=r"(r0), "=r"(r1), "=r"(r2), "=r"(r3) : "r"(a));
}
__device__ __forceinline__ void ldmx4t(uint32_t& r0, uint32_t& r1, uint32_t& r2, uint32_t& r3, uint32_t a) {
    asm volatile("ldmatrix.sync.aligned.m8n8.x4.trans.shared.b16 {%0,%1,%2,%3}, [%4];\n"
                 : "=r"(r0), "=r"(r1), "=r"(r2), "=r"(r3) : "r"(a));
}
__device__ __forceinline__ void mma16816(float* c, const uint32_t* a, uint32_t b0, uint32_t b1) {
    asm volatile("mma.sync.aligned.m16n8k16.row.col.f32.f16.f16.f32 "
                 "{%0,%1,%2,%3}, {%4,%5,%6,%7}, {%8,%9}, {%0,%1,%2,%3};\n"
                 : "+f"(c[0]), "+f"(c[1]), "+f"(c[2]), "+f"(c[3])
                 : "r"(a[0]), "r"(a[1]), "r"(a[2]), "r"(a[3]), "r"(b0), "r"(b1));
}
__device__ __forceinline__ float ex2f(float x) {
    float y; asm("ex2.approx.ftz.f32 %0, %1;" : "=f"(y) : "f"(x)); return y;
}
__device__ __forceinline__ uint32_t pack2(float x, float y) {
    __half2 h = __floats2half2_rn(x, y);
    return *reinterpret_cast<uint32_t*>(&h);
}

__global__ __launch_bounds__(128, 4)
void attn_kernel(float* __restrict__ out) {
    __shared__ __half sQ[BLKM*KPAD];
    __shared__ __half sK[BLKN*KPAD];
    __shared__ __half sV[BLKN*KPAD];

    const int tid  = threadIdx.x;
    const int warp = tid >> 5;
    const int lane = tid & 31;
    const int g    = lane >> 2;
    const int t    = lane & 3;
    const int lr   = lane & 7;
    const int grp  = lane >> 3;
    const int q0   = blockIdx.x * BLKM;
    const int bh   = blockIdx.y;

    // ---- Q tile once ----
    const __half* qg = g_q16 + ((size_t)bh*SQ + q0)*DHD;
    #pragma unroll
    for (int i = 0; i < 4; i++) {
        int idx = tid + i*128;
        int r = idx >> 3, c = (idx & 7) * 8;
        *(uint4*)&sQ[r*KPAD + c] = *(const uint4*)&qg[r*DHD + c];
    }
    __syncthreads();

    uint32_t qf[4][4];
    {
        int row = warp*16 + (grp & 1)*8 + lr;
        #pragma unroll
        for (int kt = 0; kt < 4; kt++) {
            int col = kt*16 + (grp >> 1)*8;
            ldmx4(qf[kt][0], qf[kt][1], qf[kt][2], qf[kt][3], smem_u32(&sQ[row*KPAD + col]));
        }
    }

    float acc[8][4];
    #pragma unroll
    for (int n = 0; n < 8; n++)
        #pragma unroll
        for (int x = 0; x < 4; x++) acc[n][x] = 0.f;
    float m0 = -1e30f, m1 = -1e30f, l0 = 0.f, l1 = 0.f;
    const float scl = 0.1803368801111204f;   // log2(e)/sqrt(64)

    const uint32_t* pmrow = g_pmask + ((size_t)(bh*SQ + q0))*WPR;
    const int mr0 = (warp*16 + g) * WPR;
    const int mr1 = (warp*16 + g + 8) * WPR;

    for (int j = 0; j < NITER; j++) {
        const __half* kg = g_k16 + ((size_t)bh*SQ + j*BLKN)*DHD;
        const __half* vg = g_v16 + ((size_t)bh*SQ + j*BLKN)*DHD;

        __syncthreads();
        #pragma unroll
        for (int i = 0; i < 4; i++) {
            int idx = tid + i*128;
            int r = idx >> 3, c = (idx & 7) * 8;
            *(uint4*)&sK[r*KPAD + c] = *(const uint4*)&kg[r*DHD + c];
            *(uint4*)&sV[r*KPAD + c] = *(const uint4*)&vg[r*DHD + c];
        }
        // packed mask: 64 bits per row per lane (issued early, hides under MMA)
        uint64_t mA = *(const uint64_t*)&pmrow[mr0 + 2*j];
        uint64_t mB = *(const uint64_t*)&pmrow[mr1 + 2*j];
        __syncthreads();

        // ---- S = Q K^T ----
        float s[8][4];
        #pragma unroll
        for (int n = 0; n < 8; n++)
            #pragma unroll
            for (int x = 0; x < 4; x++) s[n][x] = 0.f;

        #pragma unroll
        for (int kt = 0; kt < 4; kt++) {
            #pragma unroll
            for (int np = 0; np < 4; np++) {
                uint32_t b0, b1, b2, b3;
                int row = (2*np + (grp >> 1))*8 + lr;
                int col = kt*16 + (grp & 1)*8;
                ldmx4(b0, b1, b2, b3, smem_u32(&sK[row*KPAD + col]));
                mma16816(s[2*np],   qf[kt], b0, b1);
                mma16816(s[2*np+1], qf[kt], b2, b3);
            }
        }

        // ---- scale + mask from bits ----
        #pragma unroll
        for (int n = 0; n < 8; n++) {
            int sh = n*8 + 2*t;
            s[n][0] = ((mA >> sh)     & 1ull) ? -1e30f : s[n][0]*scl;
            s[n][1] = ((mA >> (sh+1)) & 1ull) ? -1e30f : s[n][1]*scl;
            s[n][2] = ((mB >> sh)     & 1ull) ? -1e30f : s[n][2]*scl;
            s[n][3] = ((mB >> (sh+1)) & 1ull) ? -1e30f : s[n][3]*scl;
        }

        // ---- online softmax ----
        float mx0 = -1e30f, mx1 = -1e30f;
        #pragma unroll
        for (int n = 0; n < 8; n++) {
            mx0 = fmaxf(mx0, fmaxf(s[n][0], s[n][1]));
            mx1 = fmaxf(mx1, fmaxf(s[n][2], s[n][3]));
        }
        mx0 = fmaxf(mx0, __shfl_xor_sync(0xffffffffu, mx0, 1));
        mx0 = fmaxf(mx0, __shfl_xor_sync(0xffffffffu, mx0, 2));
        mx1 = fmaxf(mx1, __shfl_xor_sync(0xffffffffu, mx1, 1));
        mx1 = fmaxf(mx1, __shfl_xor_sync(0xffffffffu, mx1, 2));

        float mn0 = fmaxf(m0, mx0), mn1 = fmaxf(m1, mx1);
        float a0 = ex2f(m0 - mn0), a1 = ex2f(m1 - mn1);
        m0 = mn0; m1 = mn1;

        float r0 = 0.f, r1 = 0.f;
        #pragma unroll
        for (int n = 0; n < 8; n++) {
            s[n][0] = ex2f(s[n][0] - mn0);
            s[n][1] = ex2f(s[n][1] - mn0);
            s[n][2] = ex2f(s[n][2] - mn1);
            s[n][3] = ex2f(s[n][3] - mn1);
            r0 += s[n][0] + s[n][1];
            r1 += s[n][2] + s[n][3];
        }
        r0 += __shfl_xor_sync(0xffffffffu, r0, 1);
        r0 += __shfl_xor_sync(0xffffffffu, r0, 2);
        r1 += __shfl_xor_sync(0xffffffffu, r1, 1);
        r1 += __shfl_xor_sync(0xffffffffu, r1, 2);
        l0 = l0*a0 + r0;
        l1 = l1*a1 + r1;

        #pragma unroll
        for (int n = 0; n < 8; n++) {
            acc[n][0] *= a0; acc[n][1] *= a0;
            acc[n][2] *= a1; acc[n][3] *= a1;
        }

        // ---- O += P V (reuse S C-layout as A-fragment) ----
        #pragma unroll
        for (int kt = 0; kt < 4; kt++) {
            uint32_t pa[4];
            pa[0] = pack2(s[2*kt][0],   s[2*kt][1]);
            pa[1] = pack2(s[2*kt][2],   s[2*kt][3]);
            pa[2] = pack2(s[2*kt+1][0], s[2*kt+1][1]);
            pa[3] = pack2(s[2*kt+1][2], s[2*kt+1][3]);
            #pragma unroll
            for (int np = 0; np < 4; np++) {
                uint32_t b0, b1, b2, b3;
                int row = kt*16 + (grp & 1)*8 + lr;
                int col = np*16 + (grp >> 1)*8;
                ldmx4t(b0, b1, b2, b3, smem_u32(&sV[row*KPAD + col]));
                mma16816(acc[2*np],   pa, b0, b1);
                mma16816(acc[2*np+1], pa, b2, b3);
            }
        }
    }

    // ---- epilogue ----
    float i0 = 1.f / l0, i1 = 1.f / l1;
    int row = q0 + warp*16 + g;
    float* op = out + ((size_t)bh*SQ + row)*DHD;
    #pragma unroll
    for (int n = 0; n < 8; n++) {
        int c0 = n*8 + 2*t;
        float2 u; u.x = acc[n][0]*i0; u.y = acc[n][1]*i0;
        *(float2*)&op[c0] = u;
        float2 w; w.x = acc[n][2]*i1; w.y = acc[n][3]*i1;
        *(float2*)&op[8*DHD + c0] = w;
    }
}

extern "C" void kernel_launch(void* const* d_in, const int* in_sizes, int n_in,
                              void* d_out, int out_size) {
    const float* q    = (const float*)d_in[0];
    const float* k    = (const float*)d_in[1];
    const float* v    = (const float*)d_in[2];
    const void*  mask = d_in[3];
    float* out = (float*)d_out;

    detect_kernel<<<1, 256>>>((const uint32_t*)mask);
    pack_kernel<<<NWORDS/256, 256>>>(mask);

    const int n4 = NBH*SQ*DHD/4;
    cvt_all_kernel<<<(n4 + 255)/256, 256>>>(q, k, v);

    dim3 grid(SQ/BLKM, NBH);
    attn_kernel<<<grid, 128>>>(out);
}